// round 2
// baseline (speedup 1.0000x reference)
#include <cuda_runtime.h>
#include <cstdint>

// ---------------------------------------------------------------------------
// S4D kernel materialization:
//   K[d,l] = 2*Re( sum_n Cc[d,n] * exp(dtA[d,n] * l) ),  D=512, N=32, L=8192
//
// Round 2: lane-pair state split (16 states/lane) + tree reduction + one
// balanced wave of 4 CTAs/SM (592 blocks = 148 * 4).
//   x_n(l) = Re(u_n * r_n^l) satisfies the stable 2-term real recurrence
//       x_{k+1} = 2Re(r^T) x_k - |r^T|^2 x_{k-1}   (stride-T sampling)
//   advanced with packed fma.rn.f32x2. Pair partials combined via shfl_xor.
// ---------------------------------------------------------------------------

#define D_MODEL 512
#define NSTATE  32
#define SEQ     8192
#define TSTRIDE 74                      // 512*74*2 lanes = 592 blocks * 128
#define MAIN_BLOCKS 592                 // = 148 SMs * 4 CTAs, one wave
#define MAIN_THREADS 128
#define EMITS 112                       // >= ceil(8192/74)=111, even

typedef unsigned long long u64;

// Precomputed per (d,n): dtA, discretized 2*Cc, r^T = exp(dtA*T)
__device__ float2 g_dtA[D_MODEL * NSTATE];
__device__ float2 g_Cc [D_MODEL * NSTATE];
__device__ float2 g_rT [D_MODEL * NSTATE];

// ---- packed f32x2 helpers --------------------------------------------------
__device__ __forceinline__ u64 pack2(float lo, float hi) {
    u64 r; asm("mov.b64 %0, {%1, %2};" : "=l"(r) : "f"(lo), "f"(hi)); return r;
}
__device__ __forceinline__ void unpack2(u64 v, float& lo, float& hi) {
    asm("mov.b64 {%0, %1}, %2;" : "=f"(lo), "=f"(hi) : "l"(v));
}
__device__ __forceinline__ u64 add2(u64 a, u64 b) {
    u64 d; asm("add.rn.f32x2 %0, %1, %2;" : "=l"(d) : "l"(a), "l"(b)); return d;
}
__device__ __forceinline__ u64 mul2(u64 a, u64 b) {
    u64 d; asm("mul.rn.f32x2 %0, %1, %2;" : "=l"(d) : "l"(a), "l"(b)); return d;
}
__device__ __forceinline__ u64 fma2(u64 a, u64 b, u64 c) {
    u64 d; asm("fma.rn.f32x2 %0, %1, %2, %3;" : "=l"(d) : "l"(a), "l"(b), "l"(c)); return d;
}

// ---------------------------------------------------------------------------
// Kernel 1: discretization precompute, one thread per (d, n). Precise math.
// ---------------------------------------------------------------------------
__global__ void s4d_precompute_kernel(const float* __restrict__ log_dt,
                                      const float* __restrict__ log_A_real,
                                      const float* __restrict__ A_imag,
                                      const float2* __restrict__ C)
{
    int i = blockIdx.x * blockDim.x + threadIdx.x;
    if (i >= D_MODEL * NSTATE) return;
    int d = i >> 5;  // / NSTATE

    float dt   = expf(log_dt[d]);
    float Ar   = -expf(log_A_real[i]);
    float Ai   = A_imag[i];
    float dtAr = Ar * dt;
    float dtAi = Ai * dt;

    // E = exp(dtA) - 1
    float er = expf(dtAr);
    float s, c;
    sincosf(dtAi, &s, &c);
    float Er = er * c - 1.0f;
    float Ei = er * s;

    // q = E / (A + 1e-8)   (1e-8 added to real part, matching reference)
    float ar8 = Ar + 1e-8f;
    float inv = 1.0f / (ar8 * ar8 + Ai * Ai);
    float qr = (Er * ar8 + Ei * Ai) * inv;
    float qi = (Ei * ar8 - Er * Ai) * inv;

    // Cc = C * q, with the final 2x output scale folded in
    float2 Cv  = C[i];
    float Ccr = 2.0f * (Cv.x * qr - Cv.y * qi);
    float Cci = 2.0f * (Cv.x * qi + Cv.y * qr);

    // r^T = exp(dtA * T)
    float eT = expf(dtAr * (float)TSTRIDE);
    float sT, cT;
    sincosf(dtAi * (float)TSTRIDE, &sT, &cT);

    g_dtA[i] = make_float2(dtAr, dtAi);
    g_Cc[i]  = make_float2(Ccr, Cci);
    g_rT[i]  = make_float2(eT * cT, eT * sT);
}

// Per-state init: exact x(t), x(t+T) and recurrence coefs (fast intrinsics,
// args bounded: |dtAr*t| <= ~8, |dtAi*t| <= ~23 -> error ~1e-5, fine).
__device__ __forceinline__ void init_state(int idx, float ft,
                                           float& xa, float& xb,
                                           float& a2, float& mn)
{
    float2 da = g_dtA[idx];
    float2 cc = g_Cc[idx];
    float2 rt = g_rT[idx];
    float e = __expf(da.x * ft);
    float s, c;
    __sincosf(da.y * ft, &s, &c);
    float wr = e * c, wi = e * s;                 // exp(dtA * t)
    float ur = cc.x * wr - cc.y * wi;             // u = Cc * exp(dtA*t)
    float ui = cc.x * wi + cc.y * wr;
    xa = ur;                                      // x(t)   = Re(u)
    xb = ur * rt.x - ui * rt.y;                   // x(t+T) = Re(u * r^T)
    a2 = rt.x + rt.x;                             // 2*Re(r^T)
    mn = -(rt.x * rt.x + rt.y * rt.y);            // -|r^T|^2
}

// Tree-reduce 8 packs -> scalar (7 add2, depth 3, then horizontal fadd).
__device__ __forceinline__ float reduce8(const u64* X)
{
    u64 s0 = add2(X[0], X[1]);
    u64 s1 = add2(X[2], X[3]);
    u64 s2 = add2(X[4], X[5]);
    u64 s3 = add2(X[6], X[7]);
    u64 t0 = add2(s0, s1);
    u64 t1 = add2(s2, s3);
    u64 u0 = add2(t0, t1);
    float lo, hi;
    unpack2(u0, lo, hi);
    return lo + hi;
}

// ---------------------------------------------------------------------------
// Kernel 2: main recurrence. Lane PAIRS cooperate on one (d, t): even lane
// owns states [0,16), odd lane [16,32). Partials combined via shfl_xor(1).
// Fixed trip count (112 emits, predicated stores) keeps control flow uniform
// so the full-mask shfl is safe and the loop unrolls.
// ---------------------------------------------------------------------------
__global__ void __launch_bounds__(MAIN_THREADS, 4)
s4d_main_kernel(float* __restrict__ out)
{
    unsigned g    = blockIdx.x * MAIN_THREADS + threadIdx.x;
    unsigned p    = g >> 1;                 // pair index -> (d, t)
    unsigned half = g & 1;
    unsigned d    = p / TSTRIDE;
    unsigned t    = p - d * TSTRIDE;
    float ft = (float)t;
    int base = (int)(d * NSTATE + half * (NSTATE / 2));

    u64 XA[8], XB[8], A2[8], MN[8];

#pragma unroll
    for (int j = 0; j < 8; j++) {
        float xa0, xb0, a20, mn0, xa1, xb1, a21, mn1;
        init_state(base + 2 * j,     ft, xa0, xb0, a20, mn0);
        init_state(base + 2 * j + 1, ft, xa1, xb1, a21, mn1);
        XA[j] = pack2(xa0, xa1);
        XB[j] = pack2(xb0, xb1);
        A2[j] = pack2(a20, a21);
        MN[j] = pack2(mn0, mn1);
    }

    float* op = out + (size_t)d * SEQ;
    int l = (int)t;

#pragma unroll 2
    for (int k = 0; k < EMITS / 2; k++) {
        // ---- emit element held in XA (even lane stores) ----
        {
            float acc   = reduce8(XA);
            float other = __shfl_xor_sync(0xffffffffu, acc, 1);
            if (half == 0 && l < SEQ) op[l] = acc + other;
        }
        l += TSTRIDE;
        // XA <- x_{k+2} = a2*XB + mn*XA
#pragma unroll
        for (int j = 0; j < 8; j++) XA[j] = fma2(A2[j], XB[j], mul2(MN[j], XA[j]));

        // ---- emit element held in XB (odd lane stores) ----
        {
            float acc   = reduce8(XB);
            float other = __shfl_xor_sync(0xffffffffu, acc, 1);
            if (half == 1 && l < SEQ) op[l] = acc + other;
        }
        l += TSTRIDE;
        // XB <- x_{k+3} = a2*XA + mn*XB
#pragma unroll
        for (int j = 0; j < 8; j++) XB[j] = fma2(A2[j], XA[j], mul2(MN[j], XB[j]));
    }
}

// ---------------------------------------------------------------------------
extern "C" void kernel_launch(void* const* d_in, const int* in_sizes, int n_in,
                              void* d_out, int out_size)
{
    const float*  log_dt     = (const float*)d_in[0];
    const float*  log_A_real = (const float*)d_in[1];
    const float*  A_imag     = (const float*)d_in[2];
    const float2* C          = (const float2*)d_in[3];
    float* out = (float*)d_out;

    s4d_precompute_kernel<<<(D_MODEL * NSTATE + 255) / 256, 256>>>(
        log_dt, log_A_real, A_imag, C);
    s4d_main_kernel<<<MAIN_BLOCKS, MAIN_THREADS>>>(out);
}

// round 3
// speedup vs baseline: 1.0598x; 1.0598x over previous
#include <cuda_runtime.h>
#include <cstdint>

// ---------------------------------------------------------------------------
// S4D kernel materialization:
//   K[d,l] = 2*Re( sum_n Cc[d,n] * exp(dtA[d,n] * l) ),  D=512, N=32, L=8192
//
// Round 3: R1 layout (32 states/thread, one balanced wave of 444 blocks),
// with (a) depth-4 tree reduction instead of a 60-cycle serial add chain,
// (b) branch-free fixed-trip mainloop (36 x 2 emits) + 2-emit tail,
// (c) pointer-increment output addressing.
//   x_n(l) = Re(u_n * r_n^l) satisfies the stable 2-term real recurrence
//       x_{k+1} = 2Re(r^T) x_k - |r^T|^2 x_{k-1}   (stride-T sampling)
//   advanced with packed fma.rn.f32x2.
// ---------------------------------------------------------------------------

#define D_MODEL 512
#define NSTATE  32
#define SEQ     8192
#define TSTRIDE 111                    // 512*111 = 56832 = 444 blocks * 128
#define MAIN_BLOCKS 444                // = 148 SMs * 3 CTAs, one wave
#define MAIN_THREADS 128

typedef unsigned long long u64;

// Precomputed per (d,n): dtA, discretized 2*Cc, r^T = exp(dtA*T)
__device__ float2 g_dtA[D_MODEL * NSTATE];
__device__ float2 g_Cc [D_MODEL * NSTATE];
__device__ float2 g_rT [D_MODEL * NSTATE];

// ---- packed f32x2 helpers --------------------------------------------------
__device__ __forceinline__ u64 pack2(float lo, float hi) {
    u64 r; asm("mov.b64 %0, {%1, %2};" : "=l"(r) : "f"(lo), "f"(hi)); return r;
}
__device__ __forceinline__ void unpack2(u64 v, float& lo, float& hi) {
    asm("mov.b64 {%0, %1}, %2;" : "=f"(lo), "=f"(hi) : "l"(v));
}
__device__ __forceinline__ u64 add2(u64 a, u64 b) {
    u64 d; asm("add.rn.f32x2 %0, %1, %2;" : "=l"(d) : "l"(a), "l"(b)); return d;
}
__device__ __forceinline__ u64 mul2(u64 a, u64 b) {
    u64 d; asm("mul.rn.f32x2 %0, %1, %2;" : "=l"(d) : "l"(a), "l"(b)); return d;
}
__device__ __forceinline__ u64 fma2(u64 a, u64 b, u64 c) {
    u64 d; asm("fma.rn.f32x2 %0, %1, %2, %3;" : "=l"(d) : "l"(a), "l"(b), "l"(c)); return d;
}

// ---------------------------------------------------------------------------
// Kernel 1: discretization precompute, one thread per (d, n). Precise math.
// ---------------------------------------------------------------------------
__global__ void s4d_precompute_kernel(const float* __restrict__ log_dt,
                                      const float* __restrict__ log_A_real,
                                      const float* __restrict__ A_imag,
                                      const float2* __restrict__ C)
{
    int i = blockIdx.x * blockDim.x + threadIdx.x;
    if (i >= D_MODEL * NSTATE) return;
    int d = i >> 5;  // / NSTATE

    float dt   = expf(log_dt[d]);
    float Ar   = -expf(log_A_real[i]);
    float Ai   = A_imag[i];
    float dtAr = Ar * dt;
    float dtAi = Ai * dt;

    // E = exp(dtA) - 1
    float er = expf(dtAr);
    float s, c;
    sincosf(dtAi, &s, &c);
    float Er = er * c - 1.0f;
    float Ei = er * s;

    // q = E / (A + 1e-8)   (1e-8 added to real part, matching reference)
    float ar8 = Ar + 1e-8f;
    float inv = 1.0f / (ar8 * ar8 + Ai * Ai);
    float qr = (Er * ar8 + Ei * Ai) * inv;
    float qi = (Ei * ar8 - Er * Ai) * inv;

    // Cc = C * q, with the final 2x output scale folded in
    float2 Cv  = C[i];
    float Ccr = 2.0f * (Cv.x * qr - Cv.y * qi);
    float Cci = 2.0f * (Cv.x * qi + Cv.y * qr);

    // r^T = exp(dtA * T)
    float eT = expf(dtAr * (float)TSTRIDE);
    float sT, cT;
    sincosf(dtAi * (float)TSTRIDE, &sT, &cT);

    g_dtA[i] = make_float2(dtAr, dtAi);
    g_Cc[i]  = make_float2(Ccr, Cci);
    g_rT[i]  = make_float2(eT * cT, eT * sT);
}

// Per-state init: exact x(t), x(t+T) and recurrence coefs (fast intrinsics,
// args bounded: |dtAr*t| <= ~10, |dtAi*t| <= ~35 -> error ~1e-5, fine).
__device__ __forceinline__ void init_state(int idx, float ft,
                                           float& xa, float& xb,
                                           float& a2, float& mn)
{
    float2 da = g_dtA[idx];
    float2 cc = g_Cc[idx];
    float2 rt = g_rT[idx];
    float e = __expf(da.x * ft);
    float s, c;
    __sincosf(da.y * ft, &s, &c);
    float wr = e * c, wi = e * s;                 // exp(dtA * t)
    float ur = cc.x * wr - cc.y * wi;             // u = Cc * exp(dtA*t)
    float ui = cc.x * wi + cc.y * wr;
    xa = ur;                                      // x(t)   = Re(u)
    xb = ur * rt.x - ui * rt.y;                   // x(t+T) = Re(u * r^T)
    a2 = rt.x + rt.x;                             // 2*Re(r^T)
    mn = -(rt.x * rt.x + rt.y * rt.y);            // -|r^T|^2
}

// Depth-4 tree reduction of 16 packs -> scalar (15 add2 + 1 fadd).
__device__ __forceinline__ float reduce16(const u64* X)
{
    u64 a0 = add2(X[0],  X[1]);
    u64 a1 = add2(X[2],  X[3]);
    u64 a2 = add2(X[4],  X[5]);
    u64 a3 = add2(X[6],  X[7]);
    u64 a4 = add2(X[8],  X[9]);
    u64 a5 = add2(X[10], X[11]);
    u64 a6 = add2(X[12], X[13]);
    u64 a7 = add2(X[14], X[15]);
    u64 b0 = add2(a0, a1);
    u64 b1 = add2(a2, a3);
    u64 b2 = add2(a4, a5);
    u64 b3 = add2(a6, a7);
    u64 c0 = add2(b0, b1);
    u64 c1 = add2(b2, b3);
    u64 d0 = add2(c0, c1);
    float lo, hi;
    unpack2(d0, lo, hi);
    return lo + hi;
}

// ---------------------------------------------------------------------------
// Kernel 2: main recurrence. One thread per (d, t), t in [0, TSTRIDE).
// Emits per thread: 74 for t < 89, else 73. Mainloop does emits 0..71 with
// no predicates or breaks; tail does emit 72 (always valid, max l = 8102)
// and emit 73 (predicated, valid iff t < 89).
// ---------------------------------------------------------------------------
__global__ void __launch_bounds__(MAIN_THREADS, 3)
s4d_main_kernel(float* __restrict__ out)
{
    unsigned g = blockIdx.x * MAIN_THREADS + threadIdx.x;
    unsigned d = g / TSTRIDE;
    unsigned t = g - d * TSTRIDE;
    float ft = (float)t;
    int base = (int)(d * NSTATE);

    u64 XA[16], XB[16], A2[16], MN[16];

#pragma unroll
    for (int j = 0; j < 16; j++) {
        float xa0, xb0, a20, mn0, xa1, xb1, a21, mn1;
        init_state(base + 2 * j,     ft, xa0, xb0, a20, mn0);
        init_state(base + 2 * j + 1, ft, xa1, xb1, a21, mn1);
        XA[j] = pack2(xa0, xa1);
        XB[j] = pack2(xb0, xb1);
        A2[j] = pack2(a20, a21);
        MN[j] = pack2(mn0, mn1);
    }

    float* op = out + (size_t)d * SEQ + t;

    // Branch-free mainloop: 36 iterations x 2 emits = emits 0..71.
    // Max address: t + 71*111 = t + 7881 <= 7991 < 8192, always in bounds.
#pragma unroll 2
    for (int k = 0; k < 36; k++) {
        // emit 2k (held in XA)
        op[0] = reduce16(XA);
        op += TSTRIDE;
        // XA <- x_{2k+2} = a2*XB + mn*XA
#pragma unroll
        for (int j = 0; j < 16; j++) XA[j] = fma2(A2[j], XB[j], mul2(MN[j], XA[j]));

        // emit 2k+1 (held in XB)
        op[0] = reduce16(XB);
        op += TSTRIDE;
        // XB <- x_{2k+3} = a2*XA + mn*XB
#pragma unroll
        for (int j = 0; j < 16; j++) XB[j] = fma2(A2[j], XA[j], mul2(MN[j], XB[j]));
    }

    // Tail: emit 72 (l = t + 7992 <= 8102, always valid), emit 73 (iff t < 89).
    op[0] = reduce16(XA);
    if (t < 89u) op[TSTRIDE] = reduce16(XB);
}

// ---------------------------------------------------------------------------
extern "C" void kernel_launch(void* const* d_in, const int* in_sizes, int n_in,
                              void* d_out, int out_size)
{
    const float*  log_dt     = (const float*)d_in[0];
    const float*  log_A_real = (const float*)d_in[1];
    const float*  A_imag     = (const float*)d_in[2];
    const float2* C          = (const float2*)d_in[3];
    float* out = (float*)d_out;

    s4d_precompute_kernel<<<(D_MODEL * NSTATE + 255) / 256, 256>>>(
        log_dt, log_A_real, A_imag, C);
    s4d_main_kernel<<<MAIN_BLOCKS, MAIN_THREADS>>>(out);
}